// round 11
// baseline (speedup 1.0000x reference)
#include <cuda_runtime.h>

#define BT 65536
#define THR_A 128
#define NBLK_A (BT / THR_A)

typedef unsigned long long ull;

// ---- device scratch (static, no runtime allocation) ----
__device__ float2 g_x2[32 * BT];     // fc1 out, paired+transposed
__device__ float  g_obsT[85 * BT];   // obs transposed
__device__ float  g_gi[192 * BT];    // gi gates, transposed [g*64+j][i]
__device__ float  g_n[64 * BT];      // candidate n, transposed
__device__ float  g_z[64 * BT];      // update gate z, transposed

__device__ __forceinline__ float lrelu(float v) { return v > 0.f ? v : 0.01f * v; }

__device__ __forceinline__ ull pack2(float lo, float hi) {
    ull r; asm("mov.b64 %0, {%1,%2};" : "=l"(r) : "f"(lo), "f"(hi)); return r;
}
__device__ __forceinline__ void unpack2(ull v, float& lo, float& hi) {
    asm("mov.b64 {%0,%1}, %2;" : "=f"(lo), "=f"(hi) : "l"(v));
}
__device__ __forceinline__ void ffma2(ull& d, ull a, ull b) {
    asm("fma.rn.f32x2 %0, %1, %2, %0;" : "+l"(d) : "l"(a), "l"(b));
}
__device__ __forceinline__ float sum2(ull v) {
    float lo, hi; unpack2(v, lo, hi); return lo + hi;
}
__device__ __forceinline__ float sigm(float x) { return 1.f / (1.f + __expf(-x)); }

// ---------------------------------------------------------------------------
// Kernel T: transpose obs -> g_obsT[85][BT]
// ---------------------------------------------------------------------------
__global__ __launch_bounds__(256) void k_tr(const float* __restrict__ obs)
{
    __shared__ float s[128 * 86];
    const int tid = threadIdx.x;
    const int i0 = blockIdx.x * 128;
    const float* src = obs + (size_t)i0 * 85;
    for (int idx = tid; idx < 10880; idx += 256) {
        int e = idx / 85, k = idx - e * 85;
        s[e * 86 + k] = src[idx];
    }
    __syncthreads();
    for (int idx = tid; idx < 10880; idx += 256) {
        int k = idx >> 7, e = idx & 127;     // 85 * 128 = 10880
        g_obsT[(size_t)k * BT + i0 + e] = s[e * 86 + k];
    }
}

// ---------------------------------------------------------------------------
// Kernel A: attention path + fc1. Static smem 34.3 KB, 20 warps/SM.
// All obs reads coalesced via g_obsT.
// ---------------------------------------------------------------------------
__global__ __launch_bounds__(THR_A, 5) void k_att(
    const float* __restrict__ w_in0, const float* __restrict__ b_in0,
    const float* __restrict__ w_in1, const float* __restrict__ b_in1,
    const float* __restrict__ w_in2, const float* __restrict__ b_in2,
    const float* __restrict__ W,     const float* __restrict__ a,
    const float* __restrict__ w_o1,  const float* __restrict__ b_o1,
    const float* __restrict__ w_o2,  const float* __restrict__ b_o2,
    const float* __restrict__ w_o3,  const float* __restrict__ b_o3,
    const float* __restrict__ w_fc1, const float* __restrict__ b_fc1)
{
    __shared__ __align__(16) float s_wfc1[5760];
    __shared__ __align__(16) float s_wint[1536];   // transposed [sel][j][f]
    __shared__ __align__(16) float s_wo1[320];
    __shared__ __align__(16) float s_wo2[512];
    __shared__ float s_bin[192];
    __shared__ __align__(8) float s_wa[128];       // (Wa1[j], Wa2[j])
    __shared__ __align__(8) float s_bo1[32];
    __shared__ __align__(8) float s_bo2[16];
    __shared__ float s_wo3[16];
    __shared__ __align__(8) float s_bfc1[64];
    __shared__ float s_bo3v[1];

    const int tid = threadIdx.x;

    // ---- Prologue 0: Wa = W @ a (W staged into s_wfc1, then overwritten) ----
    {
        float4* dW = (float4*)s_wfc1;
        const float4* sW = (const float4*)W;
        for (int idx = tid; idx < 1024; idx += THR_A) dW[idx] = sW[idx];
        __syncthreads();
        if (tid < 64) {
            const float* wr = s_wfc1 + tid * 64;
            float s1 = 0.f, s2 = 0.f;
            #pragma unroll 16
            for (int j = 0; j < 64; j++) {
                float w = wr[j];
                s1 = fmaf(w, a[j], s1);
                s2 = fmaf(w, a[64 + j], s2);
            }
            s_wa[2 * tid]     = s1;
            s_wa[2 * tid + 1] = s2;
        }
        __syncthreads();
    }

    // ---- Prologue 1: weights ----
    for (int idx = tid; idx < 1536; idx += THR_A) {
        int sel = idx >> 9, rem = idx & 511;
        int j = rem >> 3, f = rem & 7;
        const float* w = (sel == 0) ? w_in0 : ((sel == 1) ? w_in1 : w_in2);
        s_wint[idx] = w[f * 64 + j];
    }
    for (int idx = tid; idx < 192; idx += THR_A)
        s_bin[idx] = (idx < 64) ? b_in0[idx] : ((idx < 128) ? b_in1[idx - 64] : b_in2[idx - 128]);
    for (int idx = tid; idx < 320; idx += THR_A) s_wo1[idx] = w_o1[idx];
    if (tid < 32) s_bo1[tid] = b_o1[tid];
    for (int idx = tid; idx < 512; idx += THR_A) s_wo2[idx] = w_o2[idx];
    if (tid < 16) { s_bo2[tid] = b_o2[tid]; s_wo3[tid] = w_o3[tid]; }
    if (tid == 0) s_bo3v[0] = b_o3[0];
    for (int idx = tid; idx < 5760; idx += THR_A) s_wfc1[idx] = w_fc1[idx];
    if (tid < 64) s_bfc1[tid] = b_fc1[tid];
    __syncthreads();

    const int i = blockIdx.x * THR_A + tid;

    // ================= Phase 1: attention path -> obs_out =================
    float wh1[10], wh2[10];
    const ull* wa2 = (const ull*)s_wa;

    for (int t = 0; t < 10; t++) {
        const int sel = (t < 5) ? 0 : ((t < 9) ? 1 : 2);
        const float* wt = s_wint + sel * 512;
        const float* bb = s_bin + sel * 64;
        const int base = 4 + 8 * t;

        float ov[8];
        #pragma unroll
        for (int f = 0; f < 8; f++) {
            int k = base + f; if (k >= 80) k -= 80;
            ov[f] = g_obsT[(size_t)k * BT + i];        // coalesced
        }
        ull ovp[4];
        #pragma unroll
        for (int m = 0; m < 4; m++) ovp[m] = pack2(ov[2 * m], ov[2 * m + 1]);

        ull s12 = 0;
        #pragma unroll 8
        for (int j = 0; j < 64; j++) {
            const ulonglong2* wj = (const ulonglong2*)(wt + j * 8);
            ulonglong2 wA = wj[0], wB = wj[1];
            ull h2 = pack2(bb[j], 0.f);
            ffma2(h2, ovp[0], wA.x);
            ffma2(h2, ovp[1], wA.y);
            ffma2(h2, ovp[2], wB.x);
            ffma2(h2, ovp[3], wB.y);
            float hv = lrelu(sum2(h2));
            ffma2(s12, pack2(hv, hv), wa2[j]);
        }
        unpack2(s12, wh1[t], wh2[t]);
    }

    // att1 softmax stats (rows u=5..9 over cols 0..4)
    float m1[5], iz1[5];
    #pragma unroll
    for (int u = 0; u < 5; u++) {
        float e0 = lrelu(wh1[5 + u] + wh2[0]);
        float e1 = lrelu(wh1[5 + u] + wh2[1]);
        float e2 = lrelu(wh1[5 + u] + wh2[2]);
        float e3 = lrelu(wh1[5 + u] + wh2[3]);
        float e4 = lrelu(wh1[5 + u] + wh2[4]);
        float m = fmaxf(fmaxf(fmaxf(e0, e1), fmaxf(e2, e3)), e4);
        float z = __expf(e0 - m) + __expf(e1 - m) + __expf(e2 - m)
                + __expf(e3 - m) + __expf(e4 - m);
        m1[u] = m; iz1[u] = 1.f / z;
    }

    float hp3[5];
    #pragma unroll
    for (int r = 0; r < 5; r++) {
        float att[10];
        float ev[5]; float m = -1e30f;
        #pragma unroll
        for (int c = 0; c < 5; c++) { ev[c] = lrelu(wh1[r] + wh2[5 + c]); m = fmaxf(m, ev[c]); }
        float z = 0.f;
        #pragma unroll
        for (int c = 0; c < 5; c++) { ev[c] = __expf(ev[c] - m); z += ev[c]; }
        float izr = 1.f / z;
        #pragma unroll
        for (int c = 0; c < 5; c++) att[c] = ev[c] * izr;
        #pragma unroll
        for (int u = 0; u < 5; u++)
            att[5 + u] = __expf(lrelu(wh1[5 + u] + wh2[r]) - m1[u]) * iz1[u];

        ull hp1[16];
        {
            const ull* b1 = (const ull*)s_bo1;
            #pragma unroll
            for (int jj = 0; jj < 16; jj++) hp1[jj] = b1[jj];
        }
        #pragma unroll
        for (int c = 0; c < 10; c++) {
            ull av = pack2(att[c], att[c]);
            const ulonglong2* wr = (const ulonglong2*)(s_wo1 + c * 32);
            #pragma unroll
            for (int q = 0; q < 8; q++) {
                ulonglong2 w2 = wr[q];
                ffma2(hp1[2 * q], av, w2.x);
                ffma2(hp1[2 * q + 1], av, w2.y);
            }
        }
        ull hp2[8];
        {
            const ull* b2 = (const ull*)s_bo2;
            #pragma unroll
            for (int j2 = 0; j2 < 8; j2++) hp2[j2] = b2[j2];
        }
        #pragma unroll
        for (int jj = 0; jj < 16; jj++) {
            float lo, hi; unpack2(hp1[jj], lo, hi);
            {
                float v = lrelu(lo); ull vv = pack2(v, v);
                const ulonglong2* wr = (const ulonglong2*)(s_wo2 + (2 * jj) * 16);
                #pragma unroll
                for (int q = 0; q < 4; q++) {
                    ulonglong2 w2 = wr[q];
                    ffma2(hp2[2 * q], vv, w2.x);
                    ffma2(hp2[2 * q + 1], vv, w2.y);
                }
            }
            {
                float v = lrelu(hi); ull vv = pack2(v, v);
                const ulonglong2* wr = (const ulonglong2*)(s_wo2 + (2 * jj + 1) * 16);
                #pragma unroll
                for (int q = 0; q < 4; q++) {
                    ulonglong2 w2 = wr[q];
                    ffma2(hp2[2 * q], vv, w2.x);
                    ffma2(hp2[2 * q + 1], vv, w2.y);
                }
            }
        }
        float s = s_bo3v[0];
        #pragma unroll
        for (int j2 = 0; j2 < 8; j2++) {
            float lo, hi; unpack2(hp2[j2], lo, hi);
            s = fmaf(lrelu(lo), s_wo3[2 * j2], s);
            s = fmaf(lrelu(hi), s_wo3[2 * j2 + 1], s);
        }
        hp3[r] = lrelu(s);
    }

    // softmax(hp3) -> obs_out
    float oo[5];
    {
        float m = hp3[0];
        #pragma unroll
        for (int r = 1; r < 5; r++) m = fmaxf(m, hp3[r]);
        float z = 0.f;
        #pragma unroll
        for (int r = 0; r < 5; r++) { oo[r] = __expf(hp3[r] - m); z += oo[r]; }
        float iz = 1.f / z;
        #pragma unroll
        for (int r = 0; r < 5; r++) oo[r] *= iz;
    }

    // ============ Phase 2: fc1 in two 16-acc halves (regs <= ~100) ============
    #pragma unroll 1
    for (int half = 0; half < 2; half++) {
        const int jo = half * 16;      // ull offset
        ull acc[16];
        {
            const ull* bf = (const ull*)s_bfc1;
            #pragma unroll
            for (int jj = 0; jj < 16; jj++) acc[jj] = bf[jo + jj];
        }
        #pragma unroll 1
        for (int k = 0; k < 85; k++) {
            float v = g_obsT[(size_t)k * BT + i];     // coalesced, L2-resident
            ull vv = pack2(v, v);
            const ulonglong2* wr = (const ulonglong2*)(s_wfc1 + k * 64) + half * 8;
            #pragma unroll
            for (int q = 0; q < 8; q++) {
                ulonglong2 w2 = wr[q];
                ffma2(acc[2 * q], vv, w2.x);
                ffma2(acc[2 * q + 1], vv, w2.y);
            }
        }
        #pragma unroll
        for (int u = 0; u < 5; u++) {
            ull vv = pack2(oo[u], oo[u]);
            const ulonglong2* wr = (const ulonglong2*)(s_wfc1 + (85 + u) * 64) + half * 8;
            #pragma unroll
            for (int q = 0; q < 8; q++) {
                ulonglong2 w2 = wr[q];
                ffma2(acc[2 * q], vv, w2.x);
                ffma2(acc[2 * q + 1], vv, w2.y);
            }
        }
        #pragma unroll
        for (int jj = 0; jj < 16; jj++) {
            float lo, hi; unpack2(acc[jj], lo, hi);
            g_x2[(size_t)(jo + jj) * BT + i] = make_float2(fmaxf(lo, 0.f), fmaxf(hi, 0.f));
        }
    }
}

// ---------------------------------------------------------------------------
// Kernel B1: gi = x @ w_ih.T + b_ih  ->  g_gi transposed. smem 48.8 KB.
// ---------------------------------------------------------------------------
__global__ __launch_bounds__(256, 2) void k_gi(
    const float* __restrict__ w_ih, const float* __restrict__ b_ih)
{
    extern __shared__ float sm[];
    const int tid = threadIdx.x;
    {
        const float4* s4 = (const float4*)w_ih; float4* d4 = (float4*)sm;
        for (int idx = tid; idx < 3072; idx += 256) d4[idx] = s4[idx];
    }
    for (int idx = tid; idx < 192; idx += 256) sm[12288 + idx] = b_ih[idx];
    __syncthreads();

    const int i = blockIdx.x * 256 + tid;
    ull xw[32];
    #pragma unroll
    for (int m = 0; m < 32; m++) {
        float2 v = g_x2[(size_t)m * BT + i];
        xw[m] = pack2(v.x, v.y);
    }

    #pragma unroll 2
    for (int j = 0; j < 64; j++) {
        const ulonglong2* wr = (const ulonglong2*)(sm + j * 64);
        const ulonglong2* wz = (const ulonglong2*)(sm + 4096 + j * 64);
        const ulonglong2* wn = (const ulonglong2*)(sm + 8192 + j * 64);
        ull ar = 0, az = 0, an = 0;
        #pragma unroll
        for (int m2 = 0; m2 < 16; m2++) {
            ulonglong2 w;
            w = wr[m2]; ffma2(ar, xw[2 * m2], w.x); ffma2(ar, xw[2 * m2 + 1], w.y);
            w = wz[m2]; ffma2(az, xw[2 * m2], w.x); ffma2(az, xw[2 * m2 + 1], w.y);
            w = wn[m2]; ffma2(an, xw[2 * m2], w.x); ffma2(an, xw[2 * m2 + 1], w.y);
        }
        g_gi[(size_t)j * BT + i]         = sum2(ar) + sm[12288 + j];
        g_gi[(size_t)(64 + j) * BT + i]  = sum2(az) + sm[12288 + 64 + j];
        g_gi[(size_t)(128 + j) * BT + i] = sum2(an) + sm[12288 + 128 + j];
    }
}

// ---------------------------------------------------------------------------
// Kernel B2: gh dots + gate nonlinearities -> g_n, g_z. smem 48.8 KB.
// ---------------------------------------------------------------------------
__global__ __launch_bounds__(256, 2) void k_gh(
    const float* __restrict__ hidden,
    const float* __restrict__ w_hh, const float* __restrict__ b_hh)
{
    extern __shared__ float sm[];
    const int tid = threadIdx.x;
    {
        const float4* s4 = (const float4*)w_hh; float4* d4 = (float4*)sm;
        for (int idx = tid; idx < 3072; idx += 256) d4[idx] = s4[idx];
    }
    for (int idx = tid; idx < 192; idx += 256) sm[12288 + idx] = b_hh[idx];
    __syncthreads();

    const int i = blockIdx.x * 256 + tid;
    ull hw[32];
    {
        const float4* hp4 = (const float4*)(hidden + (size_t)i * 64);
        #pragma unroll
        for (int m4 = 0; m4 < 16; m4++) {
            float4 v = hp4[m4];
            hw[2 * m4]     = pack2(v.x, v.y);
            hw[2 * m4 + 1] = pack2(v.z, v.w);
        }
    }

    #pragma unroll 2
    for (int j = 0; j < 64; j++) {
        const ulonglong2* wr = (const ulonglong2*)(sm + j * 64);
        const ulonglong2* wz = (const ulonglong2*)(sm + 4096 + j * 64);
        const ulonglong2* wn = (const ulonglong2*)(sm + 8192 + j * 64);
        ull ar = 0, az = 0, an = 0;
        #pragma unroll
        for (int m2 = 0; m2 < 16; m2++) {
            ulonglong2 w;
            w = wr[m2]; ffma2(ar, hw[2 * m2], w.x); ffma2(ar, hw[2 * m2 + 1], w.y);
            w = wz[m2]; ffma2(az, hw[2 * m2], w.x); ffma2(az, hw[2 * m2 + 1], w.y);
            w = wn[m2]; ffma2(an, hw[2 * m2], w.x); ffma2(an, hw[2 * m2 + 1], w.y);
        }
        float ghr = sum2(ar) + sm[12288 + j];
        float ghz = sum2(az) + sm[12288 + 64 + j];
        float ghn = sum2(an) + sm[12288 + 128 + j];

        float gir = g_gi[(size_t)j * BT + i];
        float giz = g_gi[(size_t)(64 + j) * BT + i];
        float gin = g_gi[(size_t)(128 + j) * BT + i];

        float r  = sigm(gir + ghr);
        float zz = sigm(giz + ghz);
        float n  = 2.f * sigm(2.f * fmaf(r, ghn, gin)) - 1.f;   // tanh

        g_n[(size_t)j * BT + i] = n;
        g_z[(size_t)j * BT + i] = zz;
    }
}

// ---------------------------------------------------------------------------
// Kernel B3: blend + q head, fully unrolled (h[j] static register index).
// ---------------------------------------------------------------------------
__global__ __launch_bounds__(256) void k_fin(
    const float* __restrict__ hidden,
    const float* __restrict__ w_fc2, const float* __restrict__ b_fc2,
    float* __restrict__ out)
{
    __shared__ float s_wf[320];
    __shared__ float s_bf[5];
    const int tid = threadIdx.x;
    for (int idx = tid; idx < 320; idx += 256) s_wf[idx] = w_fc2[idx];
    if (tid < 5) s_bf[tid] = b_fc2[tid];
    __syncthreads();

    const int i = blockIdx.x * 256 + tid;
    float4 hb[16];
    {
        const float4* hp4 = (const float4*)(hidden + (size_t)i * 64);
        #pragma unroll
        for (int m = 0; m < 16; m++) hb[m] = hp4[m];
    }

    float q0 = s_bf[0], q1 = s_bf[1], q2 = s_bf[2], q3 = s_bf[3], q4 = s_bf[4];

    #pragma unroll
    for (int m = 0; m < 16; m++) {
        float4 hv = hb[m];
        #pragma unroll
        for (int c = 0; c < 4; c++) {
            const int j = 4 * m + c;
            float n = g_n[(size_t)j * BT + i];       // coalesced
            float z = g_z[(size_t)j * BT + i];       // coalesced
            float hj = (c == 0) ? hv.x : (c == 1) ? hv.y : (c == 2) ? hv.z : hv.w;
            float hnew = fmaf(z, hj - n, n);
            if (c == 0) hv.x = hnew; else if (c == 1) hv.y = hnew;
            else if (c == 2) hv.z = hnew; else hv.w = hnew;
            const float* wf = s_wf + j * 5;
            q0 = fmaf(hnew, wf[0], q0);
            q1 = fmaf(hnew, wf[1], q1);
            q2 = fmaf(hnew, wf[2], q2);
            q3 = fmaf(hnew, wf[3], q3);
            q4 = fmaf(hnew, wf[4], q4);
        }
        hb[m] = hv;
    }

    // h writeback (own row, 16 STG.128)
    {
        float4* dst = (float4*)(out + (size_t)BT * 5 + (size_t)i * 64);
        #pragma unroll
        for (int m = 0; m < 16; m++) dst[m] = hb[m];
    }
    // q writeback
    {
        float* qo = out + (size_t)i * 5;
        qo[0] = q0; qo[1] = q1; qo[2] = q2; qo[3] = q3; qo[4] = q4;
    }
}

// ---------------------------------------------------------------------------
extern "C" void kernel_launch(void* const* d_in, const int* in_sizes, int n_in,
                              void* d_out, int out_size)
{
    (void)in_sizes; (void)n_in; (void)out_size;
    const float* obs    = (const float*)d_in[0];
    const float* hidden = (const float*)d_in[1];
    const float* w_in0  = (const float*)d_in[2];
    const float* b_in0  = (const float*)d_in[3];
    const float* w_in1  = (const float*)d_in[4];
    const float* b_in1  = (const float*)d_in[5];
    const float* w_in2  = (const float*)d_in[6];
    const float* b_in2  = (const float*)d_in[7];
    const float* W      = (const float*)d_in[8];
    const float* a      = (const float*)d_in[9];
    const float* w_o1   = (const float*)d_in[10];
    const float* b_o1   = (const float*)d_in[11];
    const float* w_o2   = (const float*)d_in[12];
    const float* b_o2   = (const float*)d_in[13];
    const float* w_o3   = (const float*)d_in[14];
    const float* b_o3   = (const float*)d_in[15];
    const float* w_fc1  = (const float*)d_in[16];
    const float* b_fc1  = (const float*)d_in[17];
    const float* w_ih   = (const float*)d_in[18];
    const float* w_hh   = (const float*)d_in[19];
    const float* b_ih   = (const float*)d_in[20];
    const float* b_hh   = (const float*)d_in[21];
    const float* w_fc2  = (const float*)d_in[22];
    const float* b_fc2  = (const float*)d_in[23];

    static bool attr_done = false;
    const int smemG = 12480 * (int)sizeof(float);   // 48.75 KB
    if (!attr_done) {
        cudaFuncSetAttribute(k_gi, cudaFuncAttributeMaxDynamicSharedMemorySize, smemG);
        cudaFuncSetAttribute(k_gh, cudaFuncAttributeMaxDynamicSharedMemorySize, smemG);
        attr_done = true;
    }

    k_tr<<<BT / 128, 256>>>(obs);
    k_att<<<NBLK_A, THR_A>>>(w_in0, b_in0, w_in1, b_in1, w_in2, b_in2,
                             W, a,
                             w_o1, b_o1, w_o2, b_o2, w_o3, b_o3,
                             w_fc1, b_fc1);
    k_gi<<<BT / 256, 256, smemG>>>(w_ih, b_ih);
    k_gh<<<BT / 256, 256, smemG>>>(hidden, w_hh, b_hh);
    k_fin<<<BT / 256, 256>>>(hidden, w_fc2, b_fc2, (float*)d_out);
}

// round 12
// speedup vs baseline: 1.3236x; 1.3236x over previous
#include <cuda_runtime.h>

#define BT 65536
#define THR_A 128
#define NBLK_A (BT / THR_A)

typedef unsigned long long ull;

// ---- device scratch ----
__device__ float2 g_x2[32 * BT];     // fc1 out, paired+transposed
__device__ float  g_obsT[85 * BT];   // obs transposed

__device__ __forceinline__ float lrelu(float v) { return v > 0.f ? v : 0.01f * v; }

__device__ __forceinline__ ull pack2(float lo, float hi) {
    ull r; asm("mov.b64 %0, {%1,%2};" : "=l"(r) : "f"(lo), "f"(hi)); return r;
}
__device__ __forceinline__ void unpack2(ull v, float& lo, float& hi) {
    asm("mov.b64 {%0,%1}, %2;" : "=f"(lo), "=f"(hi) : "l"(v));
}
__device__ __forceinline__ void ffma2(ull& d, ull a, ull b) {
    asm("fma.rn.f32x2 %0, %1, %2, %0;" : "+l"(d) : "l"(a), "l"(b));
}
__device__ __forceinline__ float sum2(ull v) {
    float lo, hi; unpack2(v, lo, hi); return lo + hi;
}
__device__ __forceinline__ float sigm(float x) { return 1.f / (1.f + __expf(-x)); }

// ---------------------------------------------------------------------------
// Kernel T: transpose obs -> g_obsT[85][BT]
// ---------------------------------------------------------------------------
__global__ __launch_bounds__(256) void k_tr(const float* __restrict__ obs)
{
    __shared__ float s[128 * 86];
    const int tid = threadIdx.x;
    const int i0 = blockIdx.x * 128;
    const float* src = obs + (size_t)i0 * 85;
    for (int idx = tid; idx < 10880; idx += 256) {
        int e = idx / 85, k = idx - e * 85;
        s[e * 86 + k] = src[idx];
    }
    __syncthreads();
    for (int idx = tid; idx < 10880; idx += 256) {
        int k = idx >> 7, e = idx & 127;
        g_obsT[(size_t)k * BT + i0 + e] = s[e * 86 + k];
    }
}

// ---------------------------------------------------------------------------
// Kernel A: attention path + fc1. Static smem 34.3 KB. (128,3): no spills.
// ---------------------------------------------------------------------------
__global__ __launch_bounds__(THR_A, 3) void k_att(
    const float* __restrict__ w_in0, const float* __restrict__ b_in0,
    const float* __restrict__ w_in1, const float* __restrict__ b_in1,
    const float* __restrict__ w_in2, const float* __restrict__ b_in2,
    const float* __restrict__ W,     const float* __restrict__ a,
    const float* __restrict__ w_o1,  const float* __restrict__ b_o1,
    const float* __restrict__ w_o2,  const float* __restrict__ b_o2,
    const float* __restrict__ w_o3,  const float* __restrict__ b_o3,
    const float* __restrict__ w_fc1, const float* __restrict__ b_fc1)
{
    __shared__ __align__(16) float s_wfc1[5760];
    __shared__ __align__(16) float s_wint[1536];
    __shared__ __align__(16) float s_wo1[320];
    __shared__ __align__(16) float s_wo2[512];
    __shared__ float s_bin[192];
    __shared__ __align__(8) float s_wa[128];
    __shared__ __align__(8) float s_bo1[32];
    __shared__ __align__(8) float s_bo2[16];
    __shared__ float s_wo3[16];
    __shared__ __align__(8) float s_bfc1[64];
    __shared__ float s_bo3v[1];

    const int tid = threadIdx.x;

    // ---- Prologue 0: Wa = W @ a ----
    {
        float4* dW = (float4*)s_wfc1;
        const float4* sW = (const float4*)W;
        for (int idx = tid; idx < 1024; idx += THR_A) dW[idx] = sW[idx];
        __syncthreads();
        if (tid < 64) {
            const float* wr = s_wfc1 + tid * 64;
            float s1 = 0.f, s2 = 0.f;
            #pragma unroll 16
            for (int j = 0; j < 64; j++) {
                float w = wr[j];
                s1 = fmaf(w, a[j], s1);
                s2 = fmaf(w, a[64 + j], s2);
            }
            s_wa[2 * tid]     = s1;
            s_wa[2 * tid + 1] = s2;
        }
        __syncthreads();
    }

    // ---- Prologue 1: weights ----
    for (int idx = tid; idx < 1536; idx += THR_A) {
        int sel = idx >> 9, rem = idx & 511;
        int j = rem >> 3, f = rem & 7;
        const float* w = (sel == 0) ? w_in0 : ((sel == 1) ? w_in1 : w_in2);
        s_wint[idx] = w[f * 64 + j];
    }
    for (int idx = tid; idx < 192; idx += THR_A)
        s_bin[idx] = (idx < 64) ? b_in0[idx] : ((idx < 128) ? b_in1[idx - 64] : b_in2[idx - 128]);
    for (int idx = tid; idx < 320; idx += THR_A) s_wo1[idx] = w_o1[idx];
    if (tid < 32) s_bo1[tid] = b_o1[tid];
    for (int idx = tid; idx < 512; idx += THR_A) s_wo2[idx] = w_o2[idx];
    if (tid < 16) { s_bo2[tid] = b_o2[tid]; s_wo3[tid] = w_o3[tid]; }
    if (tid == 0) s_bo3v[0] = b_o3[0];
    for (int idx = tid; idx < 5760; idx += THR_A) s_wfc1[idx] = w_fc1[idx];
    if (tid < 64) s_bfc1[tid] = b_fc1[tid];
    __syncthreads();

    const int i = blockIdx.x * THR_A + tid;

    // ===== Phase 1: attention path =====
    float wh1[10], wh2[10];
    const ull* wa2 = (const ull*)s_wa;

    for (int t = 0; t < 10; t++) {
        const int sel = (t < 5) ? 0 : ((t < 9) ? 1 : 2);
        const float* wt = s_wint + sel * 512;
        const float* bb = s_bin + sel * 64;
        const int base = 4 + 8 * t;

        float ov[8];
        #pragma unroll
        for (int f = 0; f < 8; f++) {
            int k = base + f; if (k >= 80) k -= 80;
            ov[f] = g_obsT[(size_t)k * BT + i];
        }
        ull ovp[4];
        #pragma unroll
        for (int m = 0; m < 4; m++) ovp[m] = pack2(ov[2 * m], ov[2 * m + 1]);

        ull s12 = 0;
        #pragma unroll 8
        for (int j = 0; j < 64; j++) {
            const ulonglong2* wj = (const ulonglong2*)(wt + j * 8);
            ulonglong2 wA = wj[0], wB = wj[1];
            ull h2 = pack2(bb[j], 0.f);
            ffma2(h2, ovp[0], wA.x);
            ffma2(h2, ovp[1], wA.y);
            ffma2(h2, ovp[2], wB.x);
            ffma2(h2, ovp[3], wB.y);
            float hv = lrelu(sum2(h2));
            ffma2(s12, pack2(hv, hv), wa2[j]);
        }
        unpack2(s12, wh1[t], wh2[t]);
    }

    float m1[5], iz1[5];
    #pragma unroll
    for (int u = 0; u < 5; u++) {
        float e0 = lrelu(wh1[5 + u] + wh2[0]);
        float e1 = lrelu(wh1[5 + u] + wh2[1]);
        float e2 = lrelu(wh1[5 + u] + wh2[2]);
        float e3 = lrelu(wh1[5 + u] + wh2[3]);
        float e4 = lrelu(wh1[5 + u] + wh2[4]);
        float m = fmaxf(fmaxf(fmaxf(e0, e1), fmaxf(e2, e3)), e4);
        float z = __expf(e0 - m) + __expf(e1 - m) + __expf(e2 - m)
                + __expf(e3 - m) + __expf(e4 - m);
        m1[u] = m; iz1[u] = 1.f / z;
    }

    float hp3[5];
    #pragma unroll
    for (int r = 0; r < 5; r++) {
        float att[10];
        float ev[5]; float m = -1e30f;
        #pragma unroll
        for (int c = 0; c < 5; c++) { ev[c] = lrelu(wh1[r] + wh2[5 + c]); m = fmaxf(m, ev[c]); }
        float z = 0.f;
        #pragma unroll
        for (int c = 0; c < 5; c++) { ev[c] = __expf(ev[c] - m); z += ev[c]; }
        float izr = 1.f / z;
        #pragma unroll
        for (int c = 0; c < 5; c++) att[c] = ev[c] * izr;
        #pragma unroll
        for (int u = 0; u < 5; u++)
            att[5 + u] = __expf(lrelu(wh1[5 + u] + wh2[r]) - m1[u]) * iz1[u];

        ull hp1[16];
        {
            const ull* b1 = (const ull*)s_bo1;
            #pragma unroll
            for (int jj = 0; jj < 16; jj++) hp1[jj] = b1[jj];
        }
        #pragma unroll
        for (int c = 0; c < 10; c++) {
            ull av = pack2(att[c], att[c]);
            const ulonglong2* wr = (const ulonglong2*)(s_wo1 + c * 32);
            #pragma unroll
            for (int q = 0; q < 8; q++) {
                ulonglong2 w2 = wr[q];
                ffma2(hp1[2 * q], av, w2.x);
                ffma2(hp1[2 * q + 1], av, w2.y);
            }
        }
        ull hp2[8];
        {
            const ull* b2 = (const ull*)s_bo2;
            #pragma unroll
            for (int j2 = 0; j2 < 8; j2++) hp2[j2] = b2[j2];
        }
        #pragma unroll
        for (int jj = 0; jj < 16; jj++) {
            float lo, hi; unpack2(hp1[jj], lo, hi);
            {
                float v = lrelu(lo); ull vv = pack2(v, v);
                const ulonglong2* wr = (const ulonglong2*)(s_wo2 + (2 * jj) * 16);
                #pragma unroll
                for (int q = 0; q < 4; q++) {
                    ulonglong2 w2 = wr[q];
                    ffma2(hp2[2 * q], vv, w2.x);
                    ffma2(hp2[2 * q + 1], vv, w2.y);
                }
            }
            {
                float v = lrelu(hi); ull vv = pack2(v, v);
                const ulonglong2* wr = (const ulonglong2*)(s_wo2 + (2 * jj + 1) * 16);
                #pragma unroll
                for (int q = 0; q < 4; q++) {
                    ulonglong2 w2 = wr[q];
                    ffma2(hp2[2 * q], vv, w2.x);
                    ffma2(hp2[2 * q + 1], vv, w2.y);
                }
            }
        }
        float s = s_bo3v[0];
        #pragma unroll
        for (int j2 = 0; j2 < 8; j2++) {
            float lo, hi; unpack2(hp2[j2], lo, hi);
            s = fmaf(lrelu(lo), s_wo3[2 * j2], s);
            s = fmaf(lrelu(hi), s_wo3[2 * j2 + 1], s);
        }
        hp3[r] = lrelu(s);
    }

    float oo[5];
    {
        float m = hp3[0];
        #pragma unroll
        for (int r = 1; r < 5; r++) m = fmaxf(m, hp3[r]);
        float z = 0.f;
        #pragma unroll
        for (int r = 0; r < 5; r++) { oo[r] = __expf(hp3[r] - m); z += oo[r]; }
        float iz = 1.f / z;
        #pragma unroll
        for (int r = 0; r < 5; r++) oo[r] *= iz;
    }

    // ===== Phase 2: fc1, single 32-acc pass =====
    ull acc[32];
    {
        const ull* bf = (const ull*)s_bfc1;
        #pragma unroll
        for (int jj = 0; jj < 32; jj++) acc[jj] = bf[jj];
    }
    #pragma unroll 1
    for (int k = 0; k < 85; k++) {
        float v = g_obsT[(size_t)k * BT + i];
        ull vv = pack2(v, v);
        const ulonglong2* wr = (const ulonglong2*)(s_wfc1 + k * 64);
        #pragma unroll
        for (int q = 0; q < 16; q++) {
            ulonglong2 w2 = wr[q];
            ffma2(acc[2 * q], vv, w2.x);
            ffma2(acc[2 * q + 1], vv, w2.y);
        }
    }
    #pragma unroll
    for (int u = 0; u < 5; u++) {
        ull vv = pack2(oo[u], oo[u]);
        const ulonglong2* wr = (const ulonglong2*)(s_wfc1 + (85 + u) * 64);
        #pragma unroll
        for (int q = 0; q < 16; q++) {
            ulonglong2 w2 = wr[q];
            ffma2(acc[2 * q], vv, w2.x);
            ffma2(acc[2 * q + 1], vv, w2.y);
        }
    }
    #pragma unroll
    for (int jj = 0; jj < 32; jj++) {
        float lo, hi; unpack2(acc[jj], lo, hi);
        g_x2[(size_t)jj * BT + i] = make_float2(fmaxf(lo, 0.f), fmaxf(hi, 0.f));
    }
}

// ---------------------------------------------------------------------------
// Kernel B: fused GRU + q head, register-tiled GEMM.
// 256 elements/block (4 chunks x 64), 512 threads.
// Thread tile: 2 hidden units x 3 gates x 4 elements (elements te+16c).
// Both weight matrices smem-resident, padded rows (stride 66).
// ---------------------------------------------------------------------------
#define EB 256
#define ECH 64
#define HSTR 65        // ull stride of H rows (pad for conflict-free column reads)

#define OW_IH 0        // 192*66 = 12672
#define OW_HH 12672    // 12672
#define OBIH  25344    // 192
#define OBHH  25536    // 192
#define OWF2  25728    // 320
#define OBF2  26048    // 8
#define OQ    26056    // 320
#define OX    26376    // 32*64 ull = 4096 floats
#define OH    30472    // 32*65 ull = 4160 floats
#define SMF_G 34632    // 138.5 KB

__global__ __launch_bounds__(512, 1) void k_gru2(
    const float* __restrict__ hidden,
    const float* __restrict__ w_ih, const float* __restrict__ w_hh,
    const float* __restrict__ b_ih, const float* __restrict__ b_hh,
    const float* __restrict__ w_fc2, const float* __restrict__ b_fc2,
    float* __restrict__ out)
{
    extern __shared__ float sm[];
    ull* smX = (ull*)(sm + OX);
    ull* smH = (ull*)(sm + OH);
    const int tid = threadIdx.x;

    // ---- stage weights (padded rows), biases, fc2 ----
    for (int idx = tid; idx < 12288; idx += 512) {
        int r = idx >> 6, k = idx & 63;
        sm[OW_IH + r * 66 + k] = w_ih[idx];
        sm[OW_HH + r * 66 + k] = w_hh[idx];
    }
    for (int idx = tid; idx < 192; idx += 512) {
        sm[OBIH + idx] = b_ih[idx];
        sm[OBHH + idx] = b_hh[idx];
    }
    for (int idx = tid; idx < 320; idx += 512) sm[OWF2 + idx] = w_fc2[idx];
    if (tid < 5) sm[OBF2 + tid] = b_fc2[tid];

    const int tj = tid >> 4;          // 0..31 -> hidden pair j0=2tj
    const int te = tid & 15;          // element lane: elements te+16c
    const int j0 = 2 * tj;
    // row offsets (floats) into padded weight blocks, order: r0,r1,z0,z1,n0,n1
    const int r0 = j0 * 66,        r1 = (j0 + 1) * 66;
    const int r2 = (64 + j0) * 66, r3 = (65 + j0) * 66;
    const int r4 = (128 + j0) * 66, r5 = (129 + j0) * 66;

    #pragma unroll 1
    for (int ch = 0; ch < EB / ECH; ch++) {
        const int i0 = blockIdx.x * EB + ch * ECH;
        __syncthreads();   // previous chunk fully consumed

        // ---- stage X [k2][e] ----
        for (int idx = tid; idx < 2048; idx += 512) {
            int k2 = idx >> 6, e = idx & 63;
            float2 v = g_x2[(size_t)k2 * BT + i0 + e];
            smX[k2 * 64 + e] = pack2(v.x, v.y);
        }
        // ---- stage H [k2][e] (padded rows) ----
        for (int idx = tid; idx < 1024; idx += 512) {
            int k4 = idx >> 6, e = idx & 63;
            float4 v = *(const float4*)(hidden + (size_t)(i0 + e) * 64 + k4 * 4);
            smH[(2 * k4) * HSTR + e]     = pack2(v.x, v.y);
            smH[(2 * k4 + 1) * HSTR + e] = pack2(v.z, v.w);
        }
        __syncthreads();

        // ===== Pass A: gi = x @ w_ih.T (+b_ih), 6 rows x 4 elems =====
        ull acc[6][4];
        #pragma unroll
        for (int g = 0; g < 6; g++)
            #pragma unroll
            for (int c = 0; c < 4; c++) acc[g][c] = 0;

        #pragma unroll 4
        for (int k2 = 0; k2 < 32; k2++) {
            const int wo = 2 * k2;
            ull w0 = *(const ull*)(sm + OW_IH + r0 + wo);
            ull w1 = *(const ull*)(sm + OW_IH + r1 + wo);
            ull w2 = *(const ull*)(sm + OW_IH + r2 + wo);
            ull w3 = *(const ull*)(sm + OW_IH + r3 + wo);
            ull w4 = *(const ull*)(sm + OW_IH + r4 + wo);
            ull w5 = *(const ull*)(sm + OW_IH + r5 + wo);
            const ull* xr = smX + k2 * 64 + te;
            #pragma unroll
            for (int c = 0; c < 4; c++) {
                ull xv = xr[16 * c];
                ffma2(acc[0][c], w0, xv);
                ffma2(acc[1][c], w1, xv);
                ffma2(acc[2][c], w2, xv);
                ffma2(acc[3][c], w3, xv);
                ffma2(acc[4][c], w4, xv);
                ffma2(acc[5][c], w5, xv);
            }
        }
        float gi[6][4];
        {
            float b0 = sm[OBIH + j0],       b1 = sm[OBIH + j0 + 1];
            float b2 = sm[OBIH + 64 + j0],  b3 = sm[OBIH + 65 + j0];
            float b4 = sm[OBIH + 128 + j0], b5 = sm[OBIH + 129 + j0];
            #pragma unroll
            for (int c = 0; c < 4; c++) {
                gi[0][c] = sum2(acc[0][c]) + b0;
                gi[1][c] = sum2(acc[1][c]) + b1;
                gi[2][c] = sum2(acc[2][c]) + b2;
                gi[3][c] = sum2(acc[3][c]) + b3;
                gi[4][c] = sum2(acc[4][c]) + b4;
                gi[5][c] = sum2(acc[5][c]) + b5;
            }
        }

        // ===== Pass B: gh = h @ w_hh.T (+b_hh) =====
        #pragma unroll
        for (int g = 0; g < 6; g++)
            #pragma unroll
            for (int c = 0; c < 4; c++) acc[g][c] = 0;

        #pragma unroll 4
        for (int k2 = 0; k2 < 32; k2++) {
            const int wo = 2 * k2;
            ull w0 = *(const ull*)(sm + OW_HH + r0 + wo);
            ull w1 = *(const ull*)(sm + OW_HH + r1 + wo);
            ull w2 = *(const ull*)(sm + OW_HH + r2 + wo);
            ull w3 = *(const ull*)(sm + OW_HH + r3 + wo);
            ull w4 = *(const ull*)(sm + OW_HH + r4 + wo);
            ull w5 = *(const ull*)(sm + OW_HH + r5 + wo);
            const ull* hr = smH + k2 * HSTR + te;
            #pragma unroll
            for (int c = 0; c < 4; c++) {
                ull hv = hr[16 * c];
                ffma2(acc[0][c], w0, hv);
                ffma2(acc[1][c], w1, hv);
                ffma2(acc[2][c], w2, hv);
                ffma2(acc[3][c], w3, hv);
                ffma2(acc[4][c], w4, hv);
                ffma2(acc[5][c], w5, hv);
            }
        }
        __syncthreads();   // all H reads for dots complete chip... block-wide

        // ===== combine: gates + blend; write hnew into own H slots =====
        {
            float b0 = sm[OBHH + j0],       b1 = sm[OBHH + j0 + 1];
            float b2 = sm[OBHH + 64 + j0],  b3 = sm[OBHH + 65 + j0];
            float b4 = sm[OBHH + 128 + j0], b5 = sm[OBHH + 129 + j0];
            #pragma unroll
            for (int c = 0; c < 4; c++) {
                ull hp = smH[tj * HSTR + te + 16 * c];
                float hj0, hj1; unpack2(hp, hj0, hj1);
                float ghr0 = sum2(acc[0][c]) + b0;
                float ghr1 = sum2(acc[1][c]) + b1;
                float ghz0 = sum2(acc[2][c]) + b2;
                float ghz1 = sum2(acc[3][c]) + b3;
                float ghn0 = sum2(acc[4][c]) + b4;
                float ghn1 = sum2(acc[5][c]) + b5;

                float rr0 = sigm(gi[0][c] + ghr0);
                float rr1 = sigm(gi[1][c] + ghr1);
                float zz0 = sigm(gi[2][c] + ghz0);
                float zz1 = sigm(gi[3][c] + ghz1);
                float nn0 = 2.f * sigm(2.f * fmaf(rr0, ghn0, gi[4][c])) - 1.f;
                float nn1 = 2.f * sigm(2.f * fmaf(rr1, ghn1, gi[5][c])) - 1.f;
                float h0 = fmaf(zz0, hj0 - nn0, nn0);
                float h1 = fmaf(zz1, hj1 - nn1, nn1);
                smH[tj * HSTR + te + 16 * c] = pack2(h0, h1);
            }
        }
        __syncthreads();   // hnew visible

        // ===== q head (threads 0..63, one element each) =====
        if (tid < ECH) {
            const int e = tid;
            float q0 = sm[OBF2], q1 = sm[OBF2 + 1], q2 = sm[OBF2 + 2],
                  q3 = sm[OBF2 + 3], q4 = sm[OBF2 + 4];
            #pragma unroll 8
            for (int k2 = 0; k2 < 32; k2++) {
                ull hp = smH[k2 * HSTR + e];
                float h0, h1; unpack2(hp, h0, h1);
                const float* wf = sm + OWF2 + (2 * k2) * 5;
                q0 = fmaf(h0, wf[0], q0); q0 = fmaf(h1, wf[5], q0);
                q1 = fmaf(h0, wf[1], q1); q1 = fmaf(h1, wf[6], q1);
                q2 = fmaf(h0, wf[2], q2); q2 = fmaf(h1, wf[7], q2);
                q3 = fmaf(h0, wf[3], q3); q3 = fmaf(h1, wf[8], q3);
                q4 = fmaf(h0, wf[4], q4); q4 = fmaf(h1, wf[9], q4);
            }
            float* qd = sm + OQ + e * 5;
            qd[0] = q0; qd[1] = q1; qd[2] = q2; qd[3] = q3; qd[4] = q4;
        }

        // ===== h' writeback (coalesced: 32 k2-lanes per element row) =====
        for (int idx = tid; idx < 2048; idx += 512) {
            int e = idx >> 5, k2 = idx & 31;
            ull v = smH[k2 * HSTR + e];
            float lo, hi; unpack2(v, lo, hi);
            *(float2*)(out + (size_t)5 * BT + (size_t)(i0 + e) * 64 + 2 * k2)
                = make_float2(lo, hi);
        }
        __syncthreads();   // sm Q ready
        for (int idx = tid; idx < ECH * 5; idx += 512)
            out[(size_t)i0 * 5 + idx] = sm[OQ + idx];
    }
}

// ---------------------------------------------------------------------------
extern "C" void kernel_launch(void* const* d_in, const int* in_sizes, int n_in,
                              void* d_out, int out_size)
{
    (void)in_sizes; (void)n_in; (void)out_size;
    const float* obs    = (const float*)d_in[0];
    const float* hidden = (const float*)d_in[1];
    const float* w_in0  = (const float*)d_in[2];
    const float* b_in0  = (const float*)d_in[3];
    const float* w_in1  = (const float*)d_in[4];
    const float* b_in1  = (const float*)d_in[5];
    const float* w_in2  = (const float*)d_in[6];
    const float* b_in2  = (const float*)d_in[7];
    const float* W      = (const float*)d_in[8];
    const float* a      = (const float*)d_in[9];
    const float* w_o1   = (const float*)d_in[10];
    const float* b_o1   = (const float*)d_in[11];
    const float* w_o2   = (const float*)d_in[12];
    const float* b_o2   = (const float*)d_in[13];
    const float* w_o3   = (const float*)d_in[14];
    const float* b_o3   = (const float*)d_in[15];
    const float* w_fc1  = (const float*)d_in[16];
    const float* b_fc1  = (const float*)d_in[17];
    const float* w_ih   = (const float*)d_in[18];
    const float* w_hh   = (const float*)d_in[19];
    const float* b_ih   = (const float*)d_in[20];
    const float* b_hh   = (const float*)d_in[21];
    const float* w_fc2  = (const float*)d_in[22];
    const float* b_fc2  = (const float*)d_in[23];

    static bool attr_done = false;
    const int smemG = SMF_G * (int)sizeof(float);   // ~138.5 KB
    if (!attr_done) {
        cudaFuncSetAttribute(k_gru2, cudaFuncAttributeMaxDynamicSharedMemorySize, smemG);
        attr_done = true;
    }

    k_tr<<<BT / 128, 256>>>(obs);
    k_att<<<NBLK_A, THR_A>>>(w_in0, b_in0, w_in1, b_in1, w_in2, b_in2,
                             W, a,
                             w_o1, b_o1, w_o2, b_o2, w_o3, b_o3,
                             w_fc1, b_fc1);
    k_gru2<<<BT / EB, 512, smemG>>>(hidden, w_ih, w_hh, b_ih, b_hh,
                                    w_fc2, b_fc2, (float*)d_out);
}